// round 2
// baseline (speedup 1.0000x reference)
#include <cuda_runtime.h>

#define HWD   256
#define HW2   (HWD*HWD)        // 65536
#define NB    8
#define NC    64
#define NPIX  (NB*HW2)         // 524288
#define NPIX4 (NPIX/4)         // 131072
#define HW24  (HW2/4)          // 16384
#define TOT4  (NB*NC*HW24)     // 8388608

// Scratch (static device globals — allocation-free)
__device__ float g_n1[NPIX];
__device__ float g_n2[NPIX];
__device__ float g_r1[NPIX];
__device__ float g_r2[NPIX];

// ---------------------------------------------------------------------------
// K1: per-pixel channel L1 norms of x1 and x2.
// Threads coalesced over hw (float4), loop over 64 channels (stride HW2).
// ---------------------------------------------------------------------------
__global__ __launch_bounds__(256) void k_norm(const float4* __restrict__ x1,
                                              const float4* __restrict__ x2) {
    int i = blockIdx.x * blockDim.x + threadIdx.x;   // [0, NPIX4)
    if (i >= NPIX4) return;
    int b   = i / HW24;
    int hw4 = i - b * HW24;
    const float4* p1 = x1 + (size_t)b * NC * HW24 + hw4;
    const float4* p2 = x2 + (size_t)b * NC * HW24 + hw4;

    float4 s1 = make_float4(0.f, 0.f, 0.f, 0.f);
    float4 s2 = make_float4(0.f, 0.f, 0.f, 0.f);
#pragma unroll 8
    for (int c = 0; c < NC; ++c) {
        float4 a = p1[(size_t)c * HW24];
        float4 d = p2[(size_t)c * HW24];
        s1.x += fabsf(a.x); s1.y += fabsf(a.y); s1.z += fabsf(a.z); s1.w += fabsf(a.w);
        s2.x += fabsf(d.x); s2.y += fabsf(d.y); s2.z += fabsf(d.z); s2.w += fabsf(d.w);
    }
    reinterpret_cast<float4*>(g_n1)[i] = s1;
    reinterpret_cast<float4*>(g_n2)[i] = s2;
}

// ---------------------------------------------------------------------------
// K2: 3x3 conv (pad 1) + bias on n1/n2, then blend ratios r1, r2.
// One thread per pixel; n arrays are L2-resident (4 MB).
// ---------------------------------------------------------------------------
__global__ __launch_bounds__(256) void k_conv_ratio(const float* __restrict__ w,
                                                    const float* __restrict__ bias) {
    int i = blockIdx.x * blockDim.x + threadIdx.x;   // [0, NPIX)
    if (i >= NPIX) return;
    int b  = i >> 16;           // / HW2
    int hw = i & (HW2 - 1);
    int y  = hw >> 8;           // / HWD
    int x  = hw & (HWD - 1);

    float w00 = __ldg(w+0), w01 = __ldg(w+1), w02 = __ldg(w+2);
    float w10 = __ldg(w+3), w11 = __ldg(w+4), w12 = __ldg(w+5);
    float w20 = __ldg(w+6), w21 = __ldg(w+7), w22 = __ldg(w+8);
    float bv  = __ldg(bias);

    const float* n1 = g_n1 + b * HW2;
    const float* n2 = g_n2 + b * HW2;

    float c1 = 0.f, c2 = 0.f;
    bool ym = (y > 0), yp = (y < HWD - 1);
    bool xm = (x > 0), xp = (x < HWD - 1);
    int r0 = (y - 1) * HWD, r1r = y * HWD, r2r = (y + 1) * HWD;

    if (ym) {
        if (xm) { c1 += w00 * n1[r0 + x - 1]; c2 += w00 * n2[r0 + x - 1]; }
                  c1 += w01 * n1[r0 + x    ]; c2 += w01 * n2[r0 + x    ];
        if (xp) { c1 += w02 * n1[r0 + x + 1]; c2 += w02 * n2[r0 + x + 1]; }
    }
    if (xm) { c1 += w10 * n1[r1r + x - 1]; c2 += w10 * n2[r1r + x - 1]; }
              c1 += w11 * n1[r1r + x    ]; c2 += w11 * n2[r1r + x    ];
    if (xp) { c1 += w12 * n1[r1r + x + 1]; c2 += w12 * n2[r1r + x + 1]; }
    if (yp) {
        if (xm) { c1 += w20 * n1[r2r + x - 1]; c2 += w20 * n2[r2r + x - 1]; }
                  c1 += w21 * n1[r2r + x    ]; c2 += w21 * n2[r2r + x    ];
        if (xp) { c1 += w22 * n1[r2r + x + 1]; c2 += w22 * n2[r2r + x + 1]; }
    }
    c1 += bv;
    c2 += bv;
    float inv = 1.0f / (c1 + c2);
    g_r1[i] = c1 * inv;
    g_r2[i] = c2 * inv;
}

// ---------------------------------------------------------------------------
// K3: out = x1*r1 + x2*r2 (r broadcast across channels). Pure streaming.
// ---------------------------------------------------------------------------
__global__ __launch_bounds__(256) void k_blend(const float4* __restrict__ x1,
                                               const float4* __restrict__ x2,
                                               float4* __restrict__ out) {
    int i = blockIdx.x * blockDim.x + threadIdx.x;   // [0, TOT4)
    if (i >= TOT4) return;
    int b      = i / (NC * HW24);
    int within = i - b * (NC * HW24);
    int hw4    = within & (HW24 - 1);
    int ridx   = b * HW24 + hw4;

    float4 a  = x1[i];
    float4 d  = x2[i];
    float4 r1 = reinterpret_cast<const float4*>(g_r1)[ridx];
    float4 r2 = reinterpret_cast<const float4*>(g_r2)[ridx];

    float4 o;
    o.x = a.x * r1.x + d.x * r2.x;
    o.y = a.y * r1.y + d.y * r2.y;
    o.z = a.z * r1.z + d.z * r2.z;
    o.w = a.w * r1.w + d.w * r2.w;
    out[i] = o;
}

extern "C" void kernel_launch(void* const* d_in, const int* in_sizes, int n_in,
                              void* d_out, int out_size) {
    const float4* x1 = (const float4*)d_in[0];
    const float4* x2 = (const float4*)d_in[1];
    const float*  w  = (const float*)d_in[2];
    const float*  bv = (const float*)d_in[3];
    float4* out = (float4*)d_out;

    k_norm<<<(NPIX4 + 255) / 256, 256>>>(x1, x2);
    k_conv_ratio<<<(NPIX + 255) / 256, 256>>>(w, bv);
    k_blend<<<(TOT4 + 255) / 256, 256>>>(x1, x2, out);
}